// round 15
// baseline (speedup 1.0000x reference)
#include <cuda_runtime.h>
#include <cstdint>

// Shape (fixed by setup_inputs): B=64, T=2000, V=256, S=200, L=401
#define NEG2 -1e30f
#define VDIM 256
#define BMAX 64
#define NWIN 4                // 2-step windows per barrier block
#define ROWSPB 8              // rows consumed per barrier block
#define GHOSTL 4              // ghost lanes per warp
#define LPW 28                // real lanes per warp (28*2*4 = 224 pairs >= 201)
#define NTHR 128
#define NSTAGE 32             // cp.async ring stages (32 KB)
#define INVLN2 1.4426950408889634f
#define LN2F   0.6931471805599453f

// Cross-block scratch (device globals: no allocation).
__device__ float g_lsesum[BMAX];
__device__ int   g_flag[BMAX];

__device__ __forceinline__ float ex2f(float x) {
    float y; asm("ex2.approx.f32 %0, %1;" : "=f"(y) : "f"(x)); return y;
}
__device__ __forceinline__ float lg2f(float x) {
    float y; asm("lg2.approx.f32 %0, %1;" : "=f"(y) : "f"(x)); return y;
}

// Per-thread block-floating-point 2-step window update.
// State: alpha_i = M + lg2(s_i), s_i renormalized to [1,2) each window.
// Factors fl,fh,fm = 2^(e_row0 - b0); r1l,r1h = 2^(e_row1 - b1); K = b0+b1.
// In-loop MUFU: 2 ex2 (cross-thread scale align). No lg2, no max tree.
__device__ __forceinline__ void window_update(
    float4& s, float& M,
    float fl, float fh, float fm, float r1l, float r1h, float K,
    float g_lo, float g_hi, float g_m1, int lane)
{
    float sLm1  = __shfl_up_sync(0xFFFFFFFFu, s.w, 1);
    float sBm1  = __shfl_up_sync(0xFFFFFFFFu, s.z, 1);
    float sLm2  = __shfl_up_sync(0xFFFFFFFFu, s.y, 1);
    float Mleft = __shfl_up_sync(0xFFFFFFFFu, M, 1);
    if (lane == 0) { sLm1 = 0.0f; sBm1 = 0.0f; sLm2 = 0.0f; Mleft = M; }

    float d = M - Mleft;
    float a = ex2f(fminf(d, 0.0f));    // scales own mantissas
    float c = ex2f(fminf(-d, 0.0f));   // scales left-neighbor mantissas
    float Mref = fmaxf(M, Mleft);

    float pB0 = s.x * a, pL0 = s.y * a, pB1 = s.z * a, pL1 = s.w * a;
    float qLm1 = sLm1 * c, qBm1 = sBm1 * c, qLm2 = sLm2 * c;

    float Q   = fm * fmaf(g_m1, qLm2, qLm1 + qBm1);
    float x12 = pB0 + qLm1;
    float Ys  = fl * fmaf(g_lo, qLm1, pL0 + pB0);
    float z12 = pB1 + pL0;
    float Us  = fh * fmaf(g_hi, pL0, pL1 + pB1);

    float nB0 = x12 + Q;
    float nL0 = fmaf(g_lo, Q, Ys + x12) * r1l;
    float nB1 = z12 + Ys;
    float nL1 = fmaf(g_hi, Ys, Us + z12) * r1h;

    // Exact power-of-2 renorm: max mantissa -> [1,2).
    float m4 = fmaxf(fmaxf(nB0, nL0), fmaxf(nB1, nL1));
    int ei = ((__float_as_int(m4) >> 23) & 255) - 127;   // -127 if m4==0
    ei = min(ei, 126);
    float sc = __int_as_float((127 - ei) << 23);
    s.x = nB0 * sc; s.y = nL0 * sc; s.z = nB1 * sc; s.w = nL1 * sc;
    M = Mref + K + (float)ei;
}

// ---------------------------------------------------------------------------
// Fused kernel: blocks [0,64) = per-row LSE sums; blocks [64,128) = alpha.
// ---------------------------------------------------------------------------
__global__ __launch_bounds__(NTHR, 1)
void ctc_fused_kernel(const float* __restrict__ logits,
                      const int*  __restrict__ targets,
                      const int*  __restrict__ logits_lengths,
                      const int*  __restrict__ targets_lengths,
                      float* __restrict__ out,
                      int T, int S)
{
    const int tid  = threadIdx.x;
    const int lane = tid & 31;
    const int w    = tid >> 5;

    __shared__ __align__(16) float sh_row[NSTAGE][VDIM];
    __shared__ float4 sh_haloS[2][4][GHOSTL];
    __shared__ float  sh_haloM[2][4][GHOSTL];
    __shared__ float  sh_fin[2];
    __shared__ float  sh_part[4];

    if (blockIdx.x < BMAX) {
        // ================= LSE block =================
        const int b   = blockIdx.x;
        const int len = __ldg(&logits_lengths[b]);
        const float* __restrict__ rowp = logits + (size_t)b * T * VDIM;
        float acc = 0.0f;
        for (int t = w; t < len; t += 4) {
            const float4* r4 = reinterpret_cast<const float4*>(rowp + (size_t)t * VDIM);
            float4 a = r4[lane], c = r4[lane + 32];
            float s = __expf(a.x)+__expf(a.y)+__expf(a.z)+__expf(a.w)
                    + __expf(c.x)+__expf(c.y)+__expf(c.z)+__expf(c.w);
            #pragma unroll
            for (int o = 16; o; o >>= 1) s += __shfl_xor_sync(0xFFFFFFFFu, s, o);
            if (lane == 0) acc += __logf(s);
        }
        if (lane == 0) sh_part[w] = acc;
        __syncthreads();
        if (tid == 0) {
            g_lsesum[b] = sh_part[0] + sh_part[1] + sh_part[2] + sh_part[3];
            __threadfence();
            g_flag[b] = 1;
        }
        return;
    }

    // ================= alpha block =================
    const int b = blockIdx.x - BMAX;

    const int plo = 2 * (w * LPW + lane - GHOSTL);
    const int phi = plo + 1;
    const bool realln = (lane >= GHOSTL);

    int lblo = 0, lbhi = 0, sklo = 0, skhi = 0;
    if (plo >= 0 && plo < S) {
        lblo = __ldg(&targets[b * S + plo]);
        if (plo >= 1) sklo = (lblo != __ldg(&targets[b * S + plo - 1]));
    }
    if (phi >= 0 && phi < S) {
        lbhi = __ldg(&targets[b * S + phi]);
        skhi = (lbhi != __ldg(&targets[b * S + phi - 1]));
    }
    const float g_lo = sklo ? 1.0f : 0.0f;
    const float g_hi = skhi ? 1.0f : 0.0f;
    float g_m1 = __shfl_up_sync(0xFFFFFFFFu, g_hi, 1);
    if (lane == 0) g_m1 = 0.0f;

    // Block-floating-point state.
    float4 s = make_float4((plo == 0) ? 1.0f : 0.0f, 0.0f, 0.0f, 0.0f);
    float  M = 0.0f;

    if (lane >= 32 - GHOSTL) {
        sh_haloS[0][w][lane - (32 - GHOSTL)] = s;
        sh_haloM[0][w][lane - (32 - GHOSTL)] = M;
    }

    const int len = __ldg(&logits_lengths[b]);
    const int W   = len >> 1;
    const int odd = len & 1;
    const float* __restrict__ rowp = logits + (size_t)b * T * VDIM;

    uint32_t s_base = (uint32_t)__cvta_generic_to_shared(&sh_row[0][0]);

    // Prologue: stage rows 0..15 (2 groups of 8 rows, 16B/thread/op).
    {
        #pragma unroll
        for (int g = 0; g < 2; ++g) {
            #pragma unroll
            for (int j = 0; j < 4; ++j) {
                uint32_t off = (uint32_t)(g * 8192 + j * 2048 + tid * 16);
                uint32_t dst = s_base + off;
                const char* src = (const char*)rowp + off;
                asm volatile("cp.async.ca.shared.global [%0], [%1], 16;\n"
                             :: "r"(dst), "l"(src));
            }
            asm volatile("cp.async.commit_group;\n");
        }
        asm volatile("cp.async.wait_group 0;\n" ::: "memory");
    }
    __syncthreads();

    // Factors for block 0 (windows 0..3).
    float cfl[NWIN], cfh[NWIN], cfm[NWIN], c1l[NWIN], c1h[NWIN], cK[NWIN];
    #pragma unroll
    for (int i = 0; i < NWIN; ++i) {
        const float* r0 = &sh_row[2 * i][0];
        const float* r1 = &sh_row[2 * i + 1][0];
        float b0 = r0[0], b1 = r1[0];
        cfl[i] = ex2f((r0[lblo] - b0) * INVLN2);
        cfh[i] = ex2f((r0[lbhi] - b0) * INVLN2);
        cfm[i] = __shfl_up_sync(0xFFFFFFFFu, cfh[i], 1);
        c1l[i] = ex2f((r1[lblo] - b1) * INVLN2);
        c1h[i] = ex2f((r1[lbhi] - b1) * INVLN2);
        cK[i]  = (b0 + b1) * INVLN2;
    }

    const int nblk = (W + NWIN - 1) / NWIN;
    int par = 0;
    for (int blk = 0; blk < nblk; ++blk) {
        const int tb = blk * ROWSPB;

        // Stage rows tb+16..tb+23 (4 ops of 16B); resident through tb+15.
        {
            #pragma unroll
            for (int j = 0; j < 4; ++j) {
                const int first = tb + 16 + 2 * j;
                if (first < len) {   // pair-firsts are even; partner stays < T
                    uint32_t roff = (uint32_t)((first & (NSTAGE - 1)) * VDIM * 4
                                               + tid * 16);
                    uint32_t dst = s_base + roff;
                    const char* src = (const char*)(rowp + (size_t)first * VDIM)
                                      + tid * 16;
                    asm volatile("cp.async.ca.shared.global [%0], [%1], 16;\n"
                                 :: "r"(dst), "l"(src));
                }
            }
            asm volatile("cp.async.commit_group;\n");
            asm volatile("cp.async.wait_group 1;\n" ::: "memory");
        }
        __syncthreads();

        // Ghost refresh: per-thread (s, M) copy — no rescale needed.
        if (lane < GHOSTL && w > 0) {
            s = sh_haloS[par][w - 1][lane];
            M = sh_haloM[par][w - 1][lane];
        }

        // Prefetch next block's factors (rows tb+8..tb+15).
        float nfl[NWIN], nfh[NWIN], nfm[NWIN], n1l[NWIN], n1h[NWIN], nK[NWIN];
        #pragma unroll
        for (int i = 0; i < NWIN; ++i) {
            const int r0i = min(tb + ROWSPB + 2 * i,     len - 1);
            const int r1i = min(tb + ROWSPB + 2 * i + 1, len - 1);
            const float* r0 = &sh_row[r0i & (NSTAGE - 1)][0];
            const float* r1 = &sh_row[r1i & (NSTAGE - 1)][0];
            float b0 = r0[0], b1 = r1[0];
            nfl[i] = ex2f((r0[lblo] - b0) * INVLN2);
            nfh[i] = ex2f((r0[lbhi] - b0) * INVLN2);
            nfm[i] = __shfl_up_sync(0xFFFFFFFFu, nfh[i], 1);
            n1l[i] = ex2f((r1[lblo] - b1) * INVLN2);
            n1h[i] = ex2f((r1[lbhi] - b1) * INVLN2);
            nK[i]  = (b0 + b1) * INVLN2;
        }

        const int wbase = blk * NWIN;
        if (wbase + NWIN <= W) {
            #pragma unroll
            for (int i = 0; i < NWIN; ++i)
                window_update(s, M, cfl[i], cfh[i], cfm[i], c1l[i], c1h[i],
                              cK[i], g_lo, g_hi, g_m1, lane);
        } else {
            #pragma unroll
            for (int i = 0; i < NWIN; ++i) {
                float4 ts = s; float tM = M;
                window_update(ts, tM, cfl[i], cfh[i], cfm[i], c1l[i], c1h[i],
                              cK[i], g_lo, g_hi, g_m1, lane);
                const bool act = (wbase + i) < W;
                s = act ? ts : s;
                M = act ? tM : M;
            }
        }

        if (lane >= 32 - GHOSTL) {
            sh_haloS[par ^ 1][w][lane - (32 - GHOSTL)] = s;
            sh_haloM[par ^ 1][w][lane - (32 - GHOSTL)] = M;
        }
        par ^= 1;

        #pragma unroll
        for (int i = 0; i < NWIN; ++i) {
            cfl[i] = nfl[i]; cfh[i] = nfh[i]; cfm[i] = nfm[i];
            c1l[i] = n1l[i]; c1h[i] = n1h[i]; cK[i] = nK[i];
        }
    }

    __syncthreads();   // final halo stores visible

    if (odd) {
        // One plain 1-step update for t = len-1.
        if (lane < GHOSTL && w > 0) {
            s = sh_haloS[par][w - 1][lane];
            M = sh_haloM[par][w - 1][lane];
        }
        const float* rr = &sh_row[(len - 1) & (NSTAGE - 1)][0];
        float b0 = rr[0];
        float fL = ex2f((rr[lblo] - b0) * INVLN2);
        float fH = ex2f((rr[lbhi] - b0) * INVLN2);

        float sLm1  = __shfl_up_sync(0xFFFFFFFFu, s.w, 1);
        float Mleft = __shfl_up_sync(0xFFFFFFFFu, M, 1);
        if (lane == 0) { sLm1 = 0.0f; Mleft = M; }

        float d = M - Mleft;
        float a = ex2f(fminf(d, 0.0f));
        float c = ex2f(fminf(-d, 0.0f));
        float Mref = fmaxf(M, Mleft);

        float pB0 = s.x * a, pL0 = s.y * a, pB1 = s.z * a, pL1 = s.w * a;
        float qLm1 = sLm1 * c;

        float nB0 = pB0 + qLm1;
        float nL0 = fmaf(g_lo, qLm1, pL0 + pB0) * fL;
        float nB1 = pB1 + pL0;
        float nL1 = fmaf(g_hi, pL0, pL1 + pB1) * fH;
        s = make_float4(nB0, nL0, nB1, nL1);
        M = Mref + b0 * INVLN2;
    }

    // ---- epilogue: reconstruct log2 alphas for the final states ----
    const int tl = __ldg(&targets_lengths[b]);
    if (realln) {
        if (plo == tl - 1) sh_fin[0] = M + lg2f(s.y);   // state 2*tl - 1
        if (phi == tl - 1) sh_fin[0] = M + lg2f(s.w);
        if (plo == tl)     sh_fin[1] = M + lg2f(s.x);   // state 2*tl
        if (phi == tl)     sh_fin[1] = M + lg2f(s.z);
    }
    __syncthreads();

    if (tid == 0) {
        while (((volatile int*)g_flag)[b] == 0) { }
        const float ls = *((volatile float*)&g_lsesum[b]);
        const float f1 = sh_fin[0], f2 = sh_fin[1];   // log2 units
        const float mm = fmaxf(fmaxf(f1, f2), -1e30f);
        const float lae = mm + lg2f(ex2f(f1 - mm) + ex2f(f2 - mm));
        out[b] = ls - LN2F * lae;
    }
}

// ---------------------------------------------------------------------------
// Launch: single fused kernel, 128 blocks (64 lse + 64 alpha).
// ---------------------------------------------------------------------------
extern "C" void kernel_launch(void* const* d_in, const int* in_sizes, int n_in,
                              void* d_out, int out_size)
{
    const float* logits          = (const float*)d_in[0];
    const int*   targets         = (const int*)  d_in[1];
    const int*   logits_lengths  = (const int*)  d_in[2];
    const int*   targets_lengths = (const int*)  d_in[3];
    float*       out             = (float*)      d_out;

    const int B = in_sizes[2];               // 64
    const int S = in_sizes[1] / B;           // 200
    const int T = in_sizes[0] / (B * VDIM);  // 2000

    ctc_fused_kernel<<<2 * B, NTHR>>>(logits, targets, logits_lengths,
                                      targets_lengths, out, T, S);
}

// round 16
// speedup vs baseline: 1.0101x; 1.0101x over previous
#include <cuda_runtime.h>
#include <cstdint>

// Shape (fixed by setup_inputs): B=64, T=2000, V=256, S=200, L=401
#define NEG2 -1e30f
#define VDIM 256
#define BMAX 64
#define NWIN 6                // 2-step windows per barrier block
#define ROWSPB 12             // rows consumed per barrier block
#define GHOSTL 6              // ghost lanes per warp
#define LPW 26                // real lanes per warp (26*2*4 = 208 pairs >= 201)
#define NTHR 128
#define NSTAGE 64             // ring rows (64 KB, dynamic smem)
#define INVLN2 1.4426950408889634f
#define LN2F   0.6931471805599453f

// Dynamic smem layout (floats):
#define ROWF      (NSTAGE * VDIM)          // 16384
#define OFF_HS    ROWF                      // float4[2][4][GHOSTL] = 192 floats
#define OFF_HM    (OFF_HS + 2*4*GHOSTL*4)   // float [2][4][GHOSTL] = 48
#define OFF_FIN   (OFF_HM + 2*4*GHOSTL)
#define OFF_PART  (OFF_FIN + 2)
#define SMEM_FLOATS (OFF_PART + 8)
#define SMEM_BYTES  (SMEM_FLOATS * 4)

// Cross-block scratch (device globals: no allocation).
__device__ float g_lsesum[BMAX];
__device__ int   g_flag[BMAX];

__device__ __forceinline__ float ex2f(float x) {
    float y; asm("ex2.approx.f32 %0, %1;" : "=f"(y) : "f"(x)); return y;
}
__device__ __forceinline__ float lg2f(float x) {
    float y; asm("lg2.approx.f32 %0, %1;" : "=f"(y) : "f"(x)); return y;
}

// Per-thread block-floating-point 2-step window update (K deferred).
// State: alpha_i = M + Ksum + lg2(s_i); s renormalized to [1,2) each window.
__device__ __forceinline__ void window_update(
    float4& s, float& M,
    float fl, float fh, float fm, float r1l, float r1h,
    float g_lo, float g_hi, float g_m1, int lane)
{
    float sLm1  = __shfl_up_sync(0xFFFFFFFFu, s.w, 1);
    float sBm1  = __shfl_up_sync(0xFFFFFFFFu, s.z, 1);
    float sLm2  = __shfl_up_sync(0xFFFFFFFFu, s.y, 1);
    float Mleft = __shfl_up_sync(0xFFFFFFFFu, M, 1);
    if (lane == 0) { sLm1 = 0.0f; sBm1 = 0.0f; sLm2 = 0.0f; Mleft = M; }

    float d = M - Mleft;
    float a = ex2f(fminf(d, 0.0f));    // scales own mantissas (<=1)
    float c = ex2f(fminf(-d, 0.0f));   // scales neighbor mantissas (<=1)
    float Mref = fmaxf(M, Mleft);

    float pB0 = s.x * a, pL0 = s.y * a, pB1 = s.z * a, pL1 = s.w * a;
    float qLm1 = sLm1 * c, qBm1 = sBm1 * c, qLm2 = sLm2 * c;

    float Q   = fm * fmaf(g_m1, qLm2, qLm1 + qBm1);
    float x12 = pB0 + qLm1;
    float Ys  = fl * fmaf(g_lo, qLm1, pL0 + pB0);
    float z12 = pB1 + pL0;
    float Us  = fh * fmaf(g_hi, pL0, pL1 + pB1);

    float nB0 = x12 + Q;
    float nL0 = fmaf(g_lo, Q, Ys + x12) * r1l;
    float nB1 = z12 + Ys;
    float nL1 = fmaf(g_hi, Ys, Us + z12) * r1h;

    // Exact power-of-2 renorm: max mantissa -> [1,2).
    float m4 = fmaxf(fmaxf(nB0, nL0), fmaxf(nB1, nL1));
    int ei = ((__float_as_int(m4) >> 23) & 255) - 127;
    ei = min(ei, 126);
    float sc = __int_as_float((127 - ei) << 23);
    s.x = nB0 * sc; s.y = nL0 * sc; s.z = nB1 * sc; s.w = nL1 * sc;
    M = Mref + (float)ei;
}

// ---------------------------------------------------------------------------
// Fused kernel: blocks [0,64) = per-row LSE sums; blocks [64,128) = alpha.
// ---------------------------------------------------------------------------
__global__ __launch_bounds__(NTHR, 1)
void ctc_fused_kernel(const float* __restrict__ logits,
                      const int*  __restrict__ targets,
                      const int*  __restrict__ logits_lengths,
                      const int*  __restrict__ targets_lengths,
                      float* __restrict__ out,
                      int T, int S)
{
    extern __shared__ __align__(16) float smem[];
    const int tid  = threadIdx.x;
    const int lane = tid & 31;
    const int w    = tid >> 5;

    float  (*sh_row)[VDIM] = reinterpret_cast<float(*)[VDIM]>(smem);
    float4* sh_haloS = reinterpret_cast<float4*>(smem + OFF_HS); // [2][4][GHOSTL]
    float*  sh_haloM = smem + OFF_HM;                            // [2][4][GHOSTL]
    float*  sh_fin   = smem + OFF_FIN;
    float*  sh_part  = smem + OFF_PART;

    if (blockIdx.x < BMAX) {
        // ================= LSE block =================
        const int b   = blockIdx.x;
        const int len = __ldg(&logits_lengths[b]);
        const float* __restrict__ rowp = logits + (size_t)b * T * VDIM;
        float acc = 0.0f;
        for (int t = w; t < len; t += 4) {
            const float4* r4 = reinterpret_cast<const float4*>(rowp + (size_t)t * VDIM);
            float4 a = r4[lane], c = r4[lane + 32];
            float s = __expf(a.x)+__expf(a.y)+__expf(a.z)+__expf(a.w)
                    + __expf(c.x)+__expf(c.y)+__expf(c.z)+__expf(c.w);
            #pragma unroll
            for (int o = 16; o; o >>= 1) s += __shfl_xor_sync(0xFFFFFFFFu, s, o);
            if (lane == 0) acc += __logf(s);
        }
        if (lane == 0) sh_part[w] = acc;
        __syncthreads();
        if (tid == 0) {
            g_lsesum[b] = sh_part[0] + sh_part[1] + sh_part[2] + sh_part[3];
            __threadfence();
            g_flag[b] = 1;
        }
        return;
    }

    // ================= alpha block =================
    const int b = blockIdx.x - BMAX;

    const int plo = 2 * (w * LPW + lane - GHOSTL);
    const int phi = plo + 1;
    const bool realln = (lane >= GHOSTL);

    int lblo = 0, lbhi = 0, sklo = 0, skhi = 0;
    if (plo >= 0 && plo < S) {
        lblo = __ldg(&targets[b * S + plo]);
        if (plo >= 1) sklo = (lblo != __ldg(&targets[b * S + plo - 1]));
    }
    if (phi >= 0 && phi < S) {
        lbhi = __ldg(&targets[b * S + phi]);
        skhi = (lbhi != __ldg(&targets[b * S + phi - 1]));
    }
    const float g_lo = sklo ? 1.0f : 0.0f;
    const float g_hi = skhi ? 1.0f : 0.0f;
    float g_m1 = __shfl_up_sync(0xFFFFFFFFu, g_hi, 1);
    if (lane == 0) g_m1 = 0.0f;

    // Block-floating-point state (Ksum deferred into M at block ends).
    float4 s = make_float4((plo == 0) ? 1.0f : 0.0f, 0.0f, 0.0f, 0.0f);
    float  M = 0.0f;

    const int hidx = w * GHOSTL + (lane - (32 - GHOSTL));
    if (lane >= 32 - GHOSTL) {
        sh_haloS[hidx] = s;                 // par=0 plane
        sh_haloM[hidx] = M;
    }

    const int len = __ldg(&logits_lengths[b]);
    const int W   = len >> 1;
    const int odd = len & 1;
    const float* __restrict__ rowp = logits + (size_t)b * T * VDIM;

    uint32_t s_base = (uint32_t)__cvta_generic_to_shared(&sh_row[0][0]);
    const int subrow = tid >> 6;          // 0 or 1 (each op spans 2 rows)
    const int coloff = (tid & 63) * 16;   // byte offset within row

    // Prologue: stage rows 0..35 (3 groups of 12 rows); len >= 1500.
    {
        #pragma unroll
        for (int g = 0; g < 3; ++g) {
            #pragma unroll
            for (int j = 0; j < 6; ++j) {
                const int r = 12 * g + 2 * j + subrow;
                uint32_t dst = s_base + (uint32_t)(r * 1024 + coloff);
                const char* src = (const char*)rowp + (size_t)r * 1024 + coloff;
                asm volatile("cp.async.ca.shared.global [%0], [%1], 16;\n"
                             :: "r"(dst), "l"(src));
            }
            asm volatile("cp.async.commit_group;\n");
        }
        asm volatile("cp.async.wait_group 0;\n" ::: "memory");
    }
    __syncthreads();

    // Factors for block 0 (windows 0..5) + K sum.
    float cfl[NWIN], cfh[NWIN], cfm[NWIN], c1l[NWIN], c1h[NWIN];
    float cKsum = 0.0f;
    #pragma unroll
    for (int i = 0; i < NWIN; ++i) {
        const float* r0 = &sh_row[2 * i][0];
        const float* r1 = &sh_row[2 * i + 1][0];
        float b0 = r0[0], b1 = r1[0];
        cfl[i] = ex2f((r0[lblo] - b0) * INVLN2);
        cfh[i] = ex2f((r0[lbhi] - b0) * INVLN2);
        cfm[i] = __shfl_up_sync(0xFFFFFFFFu, cfh[i], 1);
        c1l[i] = ex2f((r1[lblo] - b1) * INVLN2);
        c1h[i] = ex2f((r1[lbhi] - b1) * INVLN2);
        cKsum += (b0 + b1) * INVLN2;
    }

    const int nblk = (W + NWIN - 1) / NWIN;
    int par = 0;
    for (int blk = 0; blk < nblk; ++blk) {
        const int tb = blk * ROWSPB;

        // Stage rows tb+36..tb+47 (one group); resident through tb+35.
        {
            #pragma unroll
            for (int j = 0; j < 6; ++j) {
                const int r = tb + 36 + 2 * j + subrow;
                if (r < len) {
                    uint32_t dst = s_base +
                        (uint32_t)((r & (NSTAGE - 1)) * 1024 + coloff);
                    const char* src = (const char*)rowp + (size_t)r * 1024 + coloff;
                    asm volatile("cp.async.ca.shared.global [%0], [%1], 16;\n"
                                 :: "r"(dst), "l"(src));
                }
            }
            asm volatile("cp.async.commit_group;\n");
            asm volatile("cp.async.wait_group 1;\n" ::: "memory");
        }
        __syncthreads();

        // Ghost refresh: per-thread (s, M) copy from left warp's tail.
        if (lane < GHOSTL && w > 0) {
            s = sh_haloS[par * (4 * GHOSTL) + (w - 1) * GHOSTL + lane];
            M = sh_haloM[par * (4 * GHOSTL) + (w - 1) * GHOSTL + lane];
        }

        // Prefetch next block's factors (rows tb+12..tb+23).
        float nfl[NWIN], nfh[NWIN], nfm[NWIN], n1l[NWIN], n1h[NWIN];
        float nKsum = 0.0f;
        #pragma unroll
        for (int i = 0; i < NWIN; ++i) {
            const int r0i = min(tb + ROWSPB + 2 * i,     len - 1);
            const int r1i = min(tb + ROWSPB + 2 * i + 1, len - 1);
            const float* r0 = &sh_row[r0i & (NSTAGE - 1)][0];
            const float* r1 = &sh_row[r1i & (NSTAGE - 1)][0];
            float b0 = r0[0], b1 = r1[0];
            nfl[i] = ex2f((r0[lblo] - b0) * INVLN2);
            nfh[i] = ex2f((r0[lbhi] - b0) * INVLN2);
            nfm[i] = __shfl_up_sync(0xFFFFFFFFu, nfh[i], 1);
            n1l[i] = ex2f((r1[lblo] - b1) * INVLN2);
            n1h[i] = ex2f((r1[lbhi] - b1) * INVLN2);
            nKsum += (b0 + b1) * INVLN2;
        }

        const int wbase = blk * NWIN;
        if (wbase + NWIN <= W) {
            #pragma unroll
            for (int i = 0; i < NWIN; ++i)
                window_update(s, M, cfl[i], cfh[i], cfm[i], c1l[i], c1h[i],
                              g_lo, g_hi, g_m1, lane);
            M += cKsum;
        } else {
            #pragma unroll
            for (int i = 0; i < NWIN; ++i) {
                float4 ts = s; float tM = M;
                window_update(ts, tM, cfl[i], cfh[i], cfm[i], c1l[i], c1h[i],
                              g_lo, g_hi, g_m1, lane);
                const bool act = (wbase + i) < W;
                if (act) {
                    // per-window K (block-uniform), recomputed from smem
                    const int r0i = (tb + 2 * i) & (NSTAGE - 1);
                    const int r1i = (tb + 2 * i + 1) & (NSTAGE - 1);
                    tM += (sh_row[r0i][0] + sh_row[r1i][0]) * INVLN2;
                    s = ts; M = tM;
                }
            }
        }

        if (lane >= 32 - GHOSTL) {
            sh_haloS[(par ^ 1) * (4 * GHOSTL) + hidx] = s;
            sh_haloM[(par ^ 1) * (4 * GHOSTL) + hidx] = M;
        }
        par ^= 1;

        #pragma unroll
        for (int i = 0; i < NWIN; ++i) {
            cfl[i] = nfl[i]; cfh[i] = nfh[i]; cfm[i] = nfm[i];
            c1l[i] = n1l[i]; c1h[i] = n1h[i];
        }
        cKsum = nKsum;
    }

    __syncthreads();   // final halo stores visible

    if (odd) {
        // One plain 1-step update for t = len-1.
        if (lane < GHOSTL && w > 0) {
            s = sh_haloS[par * (4 * GHOSTL) + (w - 1) * GHOSTL + lane];
            M = sh_haloM[par * (4 * GHOSTL) + (w - 1) * GHOSTL + lane];
        }
        const float* rr = &sh_row[(len - 1) & (NSTAGE - 1)][0];
        float b0 = rr[0];
        float fL = ex2f((rr[lblo] - b0) * INVLN2);
        float fH = ex2f((rr[lbhi] - b0) * INVLN2);

        float sLm1  = __shfl_up_sync(0xFFFFFFFFu, s.w, 1);
        float Mleft = __shfl_up_sync(0xFFFFFFFFu, M, 1);
        if (lane == 0) { sLm1 = 0.0f; Mleft = M; }

        float d = M - Mleft;
        float a = ex2f(fminf(d, 0.0f));
        float c = ex2f(fminf(-d, 0.0f));
        float Mref = fmaxf(M, Mleft);

        float pB0 = s.x * a, pL0 = s.y * a, pB1 = s.z * a, pL1 = s.w * a;
        float qLm1 = sLm1 * c;

        float nB0 = pB0 + qLm1;
        float nL0 = fmaf(g_lo, qLm1, pL0 + pB0) * fL;
        float nB1 = pB1 + pL0;
        float nL1 = fmaf(g_hi, pL0, pL1 + pB1) * fH;
        s = make_float4(nB0, nL0, nB1, nL1);
        M = Mref + b0 * INVLN2;
    }

    // ---- epilogue: reconstruct log2 alphas for the final states ----
    const int tl = __ldg(&targets_lengths[b]);
    if (realln) {
        if (plo == tl - 1) sh_fin[0] = M + lg2f(s.y);   // state 2*tl - 1
        if (phi == tl - 1) sh_fin[0] = M + lg2f(s.w);
        if (plo == tl)     sh_fin[1] = M + lg2f(s.x);   // state 2*tl
        if (phi == tl)     sh_fin[1] = M + lg2f(s.z);
    }
    __syncthreads();

    if (tid == 0) {
        while (((volatile int*)g_flag)[b] == 0) { }
        const float ls = *((volatile float*)&g_lsesum[b]);
        const float f1 = sh_fin[0], f2 = sh_fin[1];   // log2 units
        const float mm = fmaxf(fmaxf(f1, f2), -1e30f);
        const float lae = mm + lg2f(ex2f(f1 - mm) + ex2f(f2 - mm));
        out[b] = ls - LN2F * lae;
    }
}

// ---------------------------------------------------------------------------
// Launch: single fused kernel, 128 blocks (64 lse + 64 alpha), dynamic smem.
// ---------------------------------------------------------------------------
extern "C" void kernel_launch(void* const* d_in, const int* in_sizes, int n_in,
                              void* d_out, int out_size)
{
    const float* logits          = (const float*)d_in[0];
    const int*   targets         = (const int*)  d_in[1];
    const int*   logits_lengths  = (const int*)  d_in[2];
    const int*   targets_lengths = (const int*)  d_in[3];
    float*       out             = (float*)      d_out;

    const int B = in_sizes[2];               // 64
    const int S = in_sizes[1] / B;           // 200
    const int T = in_sizes[0] / (B * VDIM);  // 2000

    static int smem_set = 0;
    if (!smem_set) {
        cudaFuncSetAttribute(ctc_fused_kernel,
                             cudaFuncAttributeMaxDynamicSharedMemorySize,
                             SMEM_BYTES);
        smem_set = 1;
    }

    ctc_fused_kernel<<<2 * B, NTHR, SMEM_BYTES>>>(
        logits, targets, logits_lengths, targets_lengths, out, T, S);
}